// round 1
// baseline (speedup 1.0000x reference)
#include <cuda_runtime.h>

// Problem dims
#define M_ROWS 32768   // 8*16*256 latent vectors
#define DIM    256     // latent dim
#define KCODES 1024    // codebook size

// GEMM tiling
#define BM 128
#define BN 128
#define BK 16
#define TM 8
#define TN 8

// Scratch (no cudaMalloc allowed)
__device__ int   g_indices[M_ROWS];
__device__ float g_cnorm[KCODES];
__device__ float g_partials[2048];

// ---------------------------------------------------------------------------
// Kernel 1: codebook squared norms ||e_j||^2 (one warp per code)
// ---------------------------------------------------------------------------
__global__ void cnorm_kernel(const float* __restrict__ codebook) {
    int warp = (blockIdx.x * blockDim.x + threadIdx.x) >> 5;
    int lane = threadIdx.x & 31;
    if (warp >= KCODES) return;
    const float* row = codebook + (size_t)warp * DIM;
    float s = 0.f;
    #pragma unroll
    for (int i = 0; i < DIM / 32; ++i) {
        float v = row[lane + i * 32];
        s += v * v;
    }
    #pragma unroll
    for (int o = 16; o; o >>= 1) s += __shfl_xor_sync(0xffffffffu, s, o);
    if (lane == 0) g_cnorm[warp] = s;
}

// ---------------------------------------------------------------------------
// Kernel 2: fused distance GEMM + argmin.
// dist(n,j) = ||e_j||^2 - 2 * dot(z_n, e_j)   (||z_n||^2 dropped: row-const)
// Block: 128 rows x (all 1024 codes in 8 chunks of 128). 256 threads,
// each computes an 8x8 micro-tile, register-prefetched single-buffer smem.
// ---------------------------------------------------------------------------
__global__ __launch_bounds__(256, 2)
void argmin_kernel(const float* __restrict__ z, const float* __restrict__ cb) {
    __shared__ float As[BK][BM];
    __shared__ float Bs[BK][BN];
    __shared__ float cnorm_s[BN];
    __shared__ float redv[BM][16];
    __shared__ int   redi[BM][16];

    const int tid = threadIdx.x;
    const int tx = tid & 15;        // column group (codes)
    const int ty = tid >> 4;        // row group
    const int rowBase = blockIdx.x * BM;

    float minv[TM];
    int   mini[TM];
    #pragma unroll
    for (int i = 0; i < TM; ++i) { minv[i] = 3.4e38f; mini[i] = 0; }

    for (int chunk = 0; chunk < KCODES / BN; ++chunk) {
        const int codeBase = chunk * BN;
        float acc[TM][TN];
        #pragma unroll
        for (int i = 0; i < TM; ++i)
            #pragma unroll
            for (int j = 0; j < TN; ++j) acc[i][j] = 0.f;

        // prefetch k0 = 0
        float4 pa[2], pb[2];
        #pragma unroll
        for (int it = 0; it < 2; ++it) {
            int id = tid * 2 + it;
            int r = id >> 2, c4 = (id & 3) * 4;
            pa[it] = *(const float4*)&z [(size_t)(rowBase  + r) * DIM + 0 + c4];
            pb[it] = *(const float4*)&cb[(size_t)(codeBase + r) * DIM + 0 + c4];
        }

        for (int k0 = 0; k0 < DIM; k0 += BK) {
            // commit prefetched tile to smem (transposed)
            #pragma unroll
            for (int it = 0; it < 2; ++it) {
                int id = tid * 2 + it;
                int r = id >> 2, c4 = (id & 3) * 4;
                As[c4 + 0][r] = pa[it].x; As[c4 + 1][r] = pa[it].y;
                As[c4 + 2][r] = pa[it].z; As[c4 + 3][r] = pa[it].w;
                Bs[c4 + 0][r] = pb[it].x; Bs[c4 + 1][r] = pb[it].y;
                Bs[c4 + 2][r] = pb[it].z; Bs[c4 + 3][r] = pb[it].w;
            }
            __syncthreads();

            // issue next tile's global loads (overlap with compute)
            if (k0 + BK < DIM) {
                int kn = k0 + BK;
                #pragma unroll
                for (int it = 0; it < 2; ++it) {
                    int id = tid * 2 + it;
                    int r = id >> 2, c4 = (id & 3) * 4;
                    pa[it] = *(const float4*)&z [(size_t)(rowBase  + r) * DIM + kn + c4];
                    pb[it] = *(const float4*)&cb[(size_t)(codeBase + r) * DIM + kn + c4];
                }
            } else if (tid < BN) {
                cnorm_s[tid] = g_cnorm[codeBase + tid];
            }

            // compute
            #pragma unroll
            for (int kk = 0; kk < BK; ++kk) {
                float a[TM], b[TN];
                *(float4*)&a[0] = *(const float4*)&As[kk][ty * TM + 0];
                *(float4*)&a[4] = *(const float4*)&As[kk][ty * TM + 4];
                *(float4*)&b[0] = *(const float4*)&Bs[kk][tx * TN + 0];
                *(float4*)&b[4] = *(const float4*)&Bs[kk][tx * TN + 4];
                #pragma unroll
                for (int i = 0; i < TM; ++i)
                    #pragma unroll
                    for (int j = 0; j < TN; ++j)
                        acc[i][j] += a[i] * b[j];
            }
            __syncthreads();
        }

        // epilogue: dist = cnorm - 2*dot, running argmin (ascending index order)
        float cn[TN];
        #pragma unroll
        for (int j = 0; j < TN; ++j) cn[j] = cnorm_s[tx * TN + j];
        #pragma unroll
        for (int i = 0; i < TM; ++i) {
            #pragma unroll
            for (int j = 0; j < TN; ++j) {
                float d = cn[j] - 2.f * acc[i][j];
                int   c = codeBase + tx * TN + j;
                if (d < minv[i]) { minv[i] = d; mini[i] = c; }
            }
        }
    }

    // cross-thread argmin per row (16 column-threads per row)
    #pragma unroll
    for (int i = 0; i < TM; ++i) {
        redv[ty * TM + i][tx] = minv[i];
        redi[ty * TM + i][tx] = mini[i];
    }
    __syncthreads();
    if (tid < BM) {
        float bv = redv[tid][0];
        int   bi = redi[tid][0];
        #pragma unroll
        for (int t = 1; t < 16; ++t) {
            float v = redv[tid][t];
            int   c = redi[tid][t];
            if (v < bv || (v == bv && c < bi)) { bv = v; bi = c; }
        }
        g_indices[rowBase + tid] = bi;
    }
}

// ---------------------------------------------------------------------------
// Kernel 3: copy z_e to out, gather z_q to out (z_q_st == z_q numerically),
// accumulate per-block partial sums of (z_q - z_e)^2.
// ---------------------------------------------------------------------------
__global__ void gather_kernel(const float* __restrict__ z,
                              const float* __restrict__ cb,
                              float* __restrict__ out) {
    const int TOTAL4 = (M_ROWS * DIM) / 4;              // 8388608
    float* __restrict__ out_ze = out;                    // [0, 33554432)
    float* __restrict__ out_zq = out + (size_t)M_ROWS * DIM + 1; // 4B-aligned only

    float lsum = 0.f;
    int stride = gridDim.x * blockDim.x;
    for (int t = blockIdx.x * blockDim.x + threadIdx.x; t < TOTAL4; t += stride) {
        float4 ze = ((const float4*)z)[t];
        ((float4*)out_ze)[t] = ze;
        int row = t >> 6;                 // 64 float4 per row
        int idx = g_indices[row];
        float4 q = ((const float4*)cb)[(size_t)idx * 64 + (t & 63)];
        float dx = q.x - ze.x, dy = q.y - ze.y, dz = q.z - ze.z, dw = q.w - ze.w;
        lsum += dx * dx + dy * dy + dz * dz + dw * dw;
        size_t b = (size_t)t * 4;
        out_zq[b + 0] = q.x; out_zq[b + 1] = q.y;
        out_zq[b + 2] = q.z; out_zq[b + 3] = q.w;
    }

    __shared__ float red[256];
    red[threadIdx.x] = lsum;
    __syncthreads();
    #pragma unroll
    for (int s = 128; s; s >>= 1) {
        if (threadIdx.x < s) red[threadIdx.x] += red[threadIdx.x + s];
        __syncthreads();
    }
    if (threadIdx.x == 0) g_partials[blockIdx.x] = red[0];
}

// ---------------------------------------------------------------------------
// Kernel 4: deterministic final loss reduction.
// loss = commitment + codebook = 2 * mean((z_q - z_e)^2)
// ---------------------------------------------------------------------------
__global__ void finalize_kernel(float* __restrict__ out) {
    __shared__ float red[1024];
    int t = threadIdx.x;
    red[t] = g_partials[t] + g_partials[t + 1024];
    __syncthreads();
    #pragma unroll
    for (int s = 512; s; s >>= 1) {
        if (t < s) red[t] += red[t + s];
        __syncthreads();
    }
    if (t == 0)
        out[(size_t)M_ROWS * DIM] = 2.0f * red[0] / (float)(M_ROWS * DIM);
}

// ---------------------------------------------------------------------------
extern "C" void kernel_launch(void* const* d_in, const int* in_sizes, int n_in,
                              void* d_out, int out_size) {
    const float* z  = (const float*)d_in[0];   // z_e  [8,16,256,256]
    const float* cb = (const float*)d_in[1];   // codebook [1024,256]
    float* out = (float*)d_out;                // [z_e | loss | z_q_st]

    cnorm_kernel  <<<KCODES / 8, 256>>>(cb);
    argmin_kernel <<<M_ROWS / BM, 256>>>(z, cb);
    gather_kernel <<<2048, 256>>>(z, cb, out);
    finalize_kernel<<<1, 1024>>>(out);
}

// round 5
// speedup vs baseline: 2.9334x; 2.9334x over previous
#include <cuda_runtime.h>
#include <cuda_bf16.h>
#include <cstdint>

#define M_ROWS   32768
#define DIM      256
#define KCODES   1024
#define MARGIN   0.05f
#define CHECK_CAP 8192

// Scratch (no cudaMalloc allowed)
__device__ int   g_indices[M_ROWS];
__device__ float g_cnorm[KCODES];
__device__ float g_partials[2048];
__device__ int   g_ncheck;
__device__ int4  g_check[CHECK_CAP];

// ---------------------------------------------------------------------------
// SMEM layout (dynamic): A hi/lo resident full-K, B double-buffered k-tiles
// ---------------------------------------------------------------------------
#define SM_AHI   0
#define SM_ALO   65536
#define SM_B(buf, split) (131072 + ((buf) * 2 + (split)) * 16384)
#define SM_RED   196608
#define SM_TOTAL 204800

__device__ __forceinline__ uint32_t smem_u32(const void* p) {
    uint32_t a;
    asm("{ .reg .u64 t; cvta.to.shared.u64 t, %1; cvt.u32.u64 %0, t; }"
        : "=r"(a) : "l"(p));
    return a;
}

__device__ __forceinline__ void ldsm4(uint32_t* r, uint32_t addr) {
    asm volatile("ldmatrix.sync.aligned.m8n8.x4.shared.b16 {%0,%1,%2,%3}, [%4];"
                 : "=r"(r[0]), "=r"(r[1]), "=r"(r[2]), "=r"(r[3]) : "r"(addr));
}

__device__ __forceinline__ void mma16816(float* d, const uint32_t* a,
                                         const uint32_t* b) {
    asm volatile(
        "mma.sync.aligned.m16n8k16.row.col.f32.bf16.bf16.f32 "
        "{%0,%1,%2,%3}, {%4,%5,%6,%7}, {%8,%9}, {%0,%1,%2,%3};"
        : "+f"(d[0]), "+f"(d[1]), "+f"(d[2]), "+f"(d[3])
        : "r"(a[0]), "r"(a[1]), "r"(a[2]), "r"(a[3]), "r"(b[0]), "r"(b[1]));
}

__device__ __forceinline__ uint32_t splitpair(float x, float y, uint32_t& lo) {
    __nv_bfloat16 hx = __float2bfloat16(x), hy = __float2bfloat16(y);
    __nv_bfloat16 lx = __float2bfloat16(x - __bfloat162float(hx));
    __nv_bfloat16 ly = __float2bfloat16(y - __bfloat162float(hy));
    __nv_bfloat162 hp, lp;
    hp.x = hx; hp.y = hy; lp.x = lx; lp.y = ly;
    lo = *reinterpret_cast<uint32_t*>(&lp);
    return *reinterpret_cast<uint32_t*>(&hp);
}
__device__ __forceinline__ void split8(float4 v0, float4 v1, uint4& h, uint4& l) {
    h.x = splitpair(v0.x, v0.y, l.x);
    h.y = splitpair(v0.z, v0.w, l.y);
    h.z = splitpair(v1.x, v1.y, l.z);
    h.w = splitpair(v1.z, v1.w, l.w);
}

__device__ __forceinline__ void upd2(float& m1, int& i1, float& m2, int& i2,
                                     float d, int c) {
    if (d < m1 || (d == m1 && c < i1)) { m2 = m1; i2 = i1; m1 = d; i1 = c; }
    else if (d < m2 || (d == m2 && c < i2)) { m2 = d; i2 = c; }
}
__device__ __forceinline__ void merge2(float& m1, int& i1, float& m2, int& i2,
                                       float om1, int oi1, float om2, int oi2) {
    if (om1 < m1 || (om1 == m1 && oi1 < i1)) {
        float c = m1; int ci = i1;
        m1 = om1; i1 = oi1;
        if (om2 < c || (om2 == c && oi2 < ci)) { m2 = om2; i2 = oi2; }
        else                                   { m2 = c;   i2 = ci;  }
    } else if (om1 < m2 || (om1 == m2 && oi1 < i2)) {
        m2 = om1; i2 = oi1;
    }
}

// ---------------------------------------------------------------------------
// Kernel 1: codebook norms + zero recheck counter
// ---------------------------------------------------------------------------
__global__ void cnorm_kernel(const float* __restrict__ codebook) {
    if (blockIdx.x == 0 && threadIdx.x == 0) g_ncheck = 0;
    int warp = (blockIdx.x * blockDim.x + threadIdx.x) >> 5;
    int lane = threadIdx.x & 31;
    if (warp >= KCODES) return;
    const float* row = codebook + (size_t)warp * DIM;
    float s = 0.f;
    #pragma unroll
    for (int i = 0; i < DIM / 32; ++i) { float v = row[lane + i * 32]; s += v * v; }
    #pragma unroll
    for (int o = 16; o; o >>= 1) s += __shfl_xor_sync(0xffffffffu, s, o);
    if (lane == 0) g_cnorm[warp] = s;
}

// ---------------------------------------------------------------------------
// Kernel 2: split-bf16 distance GEMM via mma.sync + fused top-2 argmin.
// Per CTA: 128 rows x 1024 codes, K=256. dist = ||e||^2 - 2*dot.
// D = A_hi*B_hi + A_hi*B_lo + A_lo*B_hi (fp32 accum); near-ties rechecked.
// ---------------------------------------------------------------------------
__global__ __launch_bounds__(256, 1)
void argmin_mma(const float* __restrict__ z, const float* __restrict__ cb) {
    extern __shared__ char sm[];
    const int tid  = threadIdx.x;
    const int lane = tid & 31;
    const int wid  = tid >> 5;
    const int wm   = wid >> 2;      // 0..1 : M group of 64 rows
    const int wn   = wid & 3;       // 0..3 : N group of 32 codes
    const int q    = lane & 3;
    const int rowBase = blockIdx.x * 128;
    const uint32_t sbase = smem_u32(sm);

    // ---- A prologue: z rows -> split bf16 hi/lo, swizzled 16B chunks ----
    #pragma unroll
    for (int it = 0; it < 16; ++it) {
        int idx = it * 256 + tid;          // [0, 4096): 128 rows x 32 chunks
        int r = idx >> 5, kc = idx & 31;
        const float4* src = (const float4*)(z + (size_t)(rowBase + r) * DIM + kc * 8);
        float4 v0 = src[0], v1 = src[1];
        uint4 h, l;
        split8(v0, v1, h, l);
        uint32_t off = (uint32_t)(r * 512 + ((kc ^ (r & 7)) << 4));
        *(uint4*)(sm + SM_AHI + off) = h;
        *(uint4*)(sm + SM_ALO + off) = l;
    }

    float tm1[8], tm2[8];
    int   ti1[8], ti2[8];
    #pragma unroll
    for (int s = 0; s < 8; ++s) {
        tm1[s] = 3.4e38f; tm2[s] = 3.4e38f;
        ti1[s] = 0x7fffffff; ti2[s] = 0x7fffffff;
    }

    for (int chunk = 0; chunk < 8; ++chunk) {
        const int codeBase = chunk * 128;

        float acc[4][4][4];
        #pragma unroll
        for (int mt = 0; mt < 4; ++mt)
            #pragma unroll
            for (int nt = 0; nt < 4; ++nt)
                #pragma unroll
                for (int e = 0; e < 4; ++e) acc[mt][nt][e] = 0.f;

        float cn[4][2];
        #pragma unroll
        for (int nt = 0; nt < 4; ++nt) {
            int c0 = codeBase + wn * 32 + nt * 8 + 2 * q;
            cn[nt][0] = g_cnorm[c0];
            cn[nt][1] = g_cnorm[c0 + 1];
        }

        // produce k-tile 0 into buf 0 (direct LDG -> split -> STS)
        #pragma unroll
        for (int it = 0; it < 2; ++it) {
            int idx = it * 256 + tid;      // [0, 512): 128 codes x 4 chunks
            int n = idx >> 2, kkc = idx & 3;
            const float4* src = (const float4*)(cb + (size_t)(codeBase + n) * DIM + kkc * 8);
            float4 v0 = src[0], v1 = src[1];
            uint4 h, l;
            split8(v0, v1, h, l);
            uint32_t off = (uint32_t)(n * 128 + ((kkc ^ (n & 7)) << 4));
            *(uint4*)(sm + SM_B(0, 0) + off) = h;
            *(uint4*)(sm + SM_B(0, 1) + off) = l;
        }

        for (int kt = 0; kt < 8; ++kt) {
            __syncthreads();               // buf[kt&1] ready; prev mma drained
            const int buf = kt & 1;

            // stage LDG for next k-tile (overlaps with mma below)
            float4 stg[4];
            if (kt < 7) {
                #pragma unroll
                for (int it = 0; it < 2; ++it) {
                    int idx = it * 256 + tid;
                    int n = idx >> 2, kkc = idx & 3;
                    const float4* src = (const float4*)
                        (cb + (size_t)(codeBase + n) * DIM + (kt + 1) * 32 + kkc * 8);
                    stg[it * 2 + 0] = src[0];
                    stg[it * 2 + 1] = src[1];
                }
            }

            // mma over buf, 2 k-steps of 16
            #pragma unroll
            for (int ks = 0; ks < 2; ++ks) {
                const int kA = kt * 32 + ks * 16;
                const int rA = lane & 15;
                const int half = lane >> 4;

                uint32_t a_hi[4][4], a_lo[4][4];
                #pragma unroll
                for (int mt = 0; mt < 4; ++mt) {
                    int row = wm * 64 + mt * 16 + rA;
                    uint32_t off = (uint32_t)(row * 512 +
                        ((((kA >> 3) + half) ^ (row & 7)) << 4));
                    ldsm4(a_hi[mt], sbase + SM_AHI + off);
                    ldsm4(a_lo[mt], sbase + SM_ALO + off);
                }
                uint32_t b_hi[2][4], b_lo[2][4];
                #pragma unroll
                for (int ntp = 0; ntp < 2; ++ntp) {
                    int n = wn * 32 + ntp * 16 + ((lane >> 4) << 3) + (lane & 7);
                    int c = ks * 2 + ((lane >> 3) & 1);
                    uint32_t off = (uint32_t)(n * 128 + ((c ^ (n & 7)) << 4));
                    ldsm4(b_hi[ntp], sbase + SM_B(buf, 0) + off);
                    ldsm4(b_lo[ntp], sbase + SM_B(buf, 1) + off);
                }
                #pragma unroll
                for (int mt = 0; mt < 4; ++mt)
                    #pragma unroll
                    for (int nt = 0; nt < 4; ++nt) {
                        const uint32_t* bh = &b_hi[nt >> 1][(nt & 1) * 2];
                        const uint32_t* bl = &b_lo[nt >> 1][(nt & 1) * 2];
                        mma16816(acc[mt][nt], a_hi[mt], bh);
                        mma16816(acc[mt][nt], a_hi[mt], bl);
                        mma16816(acc[mt][nt], a_lo[mt], bh);
                    }
            }

            // convert + STS next k-tile into the other buffer
            if (kt < 7) {
                #pragma unroll
                for (int it = 0; it < 2; ++it) {
                    int idx = it * 256 + tid;
                    int n = idx >> 2, kkc = idx & 3;
                    uint4 h, l;
                    split8(stg[it * 2 + 0], stg[it * 2 + 1], h, l);
                    uint32_t off = (uint32_t)(n * 128 + ((kkc ^ (n & 7)) << 4));
                    *(uint4*)(sm + SM_B(buf ^ 1, 0) + off) = h;
                    *(uint4*)(sm + SM_B(buf ^ 1, 1) + off) = l;
                }
            }
        }

        // chunk epilogue: dist = cn - 2*dot, per-thread top-2 update
        #pragma unroll
        for (int mt = 0; mt < 4; ++mt)
            #pragma unroll
            for (int nt = 0; nt < 4; ++nt) {
                int col = codeBase + wn * 32 + nt * 8 + 2 * q;
                #pragma unroll
                for (int hh = 0; hh < 2; ++hh) {
                    int s = mt * 2 + hh;
                    float d0 = fmaf(-2.f, acc[mt][nt][hh * 2 + 0], cn[nt][0]);
                    float d1 = fmaf(-2.f, acc[mt][nt][hh * 2 + 1], cn[nt][1]);
                    upd2(tm1[s], ti1[s], tm2[s], ti2[s], d0, col);
                    upd2(tm1[s], ti1[s], tm2[s], ti2[s], d1, col + 1);
                }
            }
    }

    // ---- final reduce: quad shuffle, then across the 4 N-warps via SMEM ----
    float4* red = (float4*)(sm + SM_RED);   // [128 rows][4 wn]
    #pragma unroll
    for (int s = 0; s < 8; ++s) {
        float m1 = tm1[s], m2 = tm2[s];
        int   i1 = ti1[s], i2 = ti2[s];
        #pragma unroll
        for (int off = 1; off <= 2; off <<= 1) {
            float om1 = __shfl_xor_sync(0xffffffffu, m1, off);
            int   oi1 = __shfl_xor_sync(0xffffffffu, i1, off);
            float om2 = __shfl_xor_sync(0xffffffffu, m2, off);
            int   oi2 = __shfl_xor_sync(0xffffffffu, i2, off);
            merge2(m1, i1, m2, i2, om1, oi1, om2, oi2);
        }
        if (q == 0) {
            int mt = s >> 1, hh = s & 1;
            int row = wm * 64 + mt * 16 + hh * 8 + (lane >> 2);
            red[row * 4 + wn] = make_float4(m1, __int_as_float(i1),
                                            m2, __int_as_float(i2));
        }
    }
    __syncthreads();

    if (tid < 128) {
        float4 p = red[tid * 4 + 0];
        float m1 = p.x, m2 = p.z;
        int   i1 = __float_as_int(p.y), i2 = __float_as_int(p.w);
        #pragma unroll
        for (int w = 1; w < 4; ++w) {
            float4 o = red[tid * 4 + w];
            merge2(m1, i1, m2, i2, o.x, __float_as_int(o.y),
                   o.z, __float_as_int(o.w));
        }
        int row = rowBase + tid;
        g_indices[row] = i1;
        if (m2 - m1 <= MARGIN) {
            int slot = atomicAdd(&g_ncheck, 1);
            if (slot < CHECK_CAP) g_check[slot] = make_int4(row, i1, i2, 0);
        }
    }
}

// ---------------------------------------------------------------------------
// Kernel 3: exact fp32 recheck of queued near-tie rows (one warp per entry)
// ---------------------------------------------------------------------------
__global__ void recheck_kernel(const float* __restrict__ z,
                               const float* __restrict__ cb) {
    int nw = (gridDim.x * blockDim.x) >> 5;
    int w = (blockIdx.x * blockDim.x + threadIdx.x) >> 5;
    int lane = threadIdx.x & 31;
    int n = g_ncheck; if (n > CHECK_CAP) n = CHECK_CAP;
    for (int e = w; e < n; e += nw) {
        int4 ent = g_check[e];
        const float* zr = z  + (size_t)ent.x * DIM;
        const float* e1 = cb + (size_t)ent.y * DIM;
        const float* e2 = cb + (size_t)ent.z * DIM;
        float d1 = 0.f, d2 = 0.f;
        for (int i = lane; i < DIM; i += 32) {
            float zv = zr[i];
            float a = zv - e1[i]; d1 += a * a;
            float b = zv - e2[i]; d2 += b * b;
        }
        #pragma unroll
        for (int o = 16; o; o >>= 1) {
            d1 += __shfl_xor_sync(0xffffffffu, d1, o);
            d2 += __shfl_xor_sync(0xffffffffu, d2, o);
        }
        if (lane == 0) {
            int best = (d1 < d2) ? ent.y : ((d2 < d1) ? ent.z
                        : (ent.y < ent.z ? ent.y : ent.z));
            g_indices[ent.x] = best;
        }
    }
}

// ---------------------------------------------------------------------------
// Kernel 4: copy z_e, gather z_q (z_q_st == z_q), partial loss sums
// ---------------------------------------------------------------------------
__global__ void gather_kernel(const float* __restrict__ z,
                              const float* __restrict__ cb,
                              float* __restrict__ out) {
    const int TOTAL4 = (M_ROWS * DIM) / 4;
    float* __restrict__ out_ze = out;
    float* __restrict__ out_zq = out + (size_t)M_ROWS * DIM + 1;

    float lsum = 0.f;
    int stride = gridDim.x * blockDim.x;
    for (int t = blockIdx.x * blockDim.x + threadIdx.x; t < TOTAL4; t += stride) {
        float4 ze = ((const float4*)z)[t];
        ((float4*)out_ze)[t] = ze;
        int row = t >> 6;
        int idx = g_indices[row];
        float4 qv = ((const float4*)cb)[(size_t)idx * 64 + (t & 63)];
        float dx = qv.x - ze.x, dy = qv.y - ze.y;
        float dz = qv.z - ze.z, dw = qv.w - ze.w;
        lsum += dx * dx + dy * dy + dz * dz + dw * dw;
        size_t b = (size_t)t * 4;
        out_zq[b + 0] = qv.x; out_zq[b + 1] = qv.y;
        out_zq[b + 2] = qv.z; out_zq[b + 3] = qv.w;
    }

    __shared__ float red[256];
    red[threadIdx.x] = lsum;
    __syncthreads();
    #pragma unroll
    for (int s = 128; s; s >>= 1) {
        if (threadIdx.x < s) red[threadIdx.x] += red[threadIdx.x + s];
        __syncthreads();
    }
    if (threadIdx.x == 0) g_partials[blockIdx.x] = red[0];
}

// ---------------------------------------------------------------------------
// Kernel 5: deterministic final loss
// ---------------------------------------------------------------------------
__global__ void finalize_kernel(float* __restrict__ out) {
    __shared__ float red[1024];
    int t = threadIdx.x;
    red[t] = g_partials[t] + g_partials[t + 1024];
    __syncthreads();
    #pragma unroll
    for (int s = 512; s; s >>= 1) {
        if (t < s) red[t] += red[t + s];
        __syncthreads();
    }
    if (t == 0)
        out[(size_t)M_ROWS * DIM] = 2.0f * red[0] / (float)(M_ROWS * DIM);
}

// ---------------------------------------------------------------------------
extern "C" void kernel_launch(void* const* d_in, const int* in_sizes, int n_in,
                              void* d_out, int out_size) {
    const float* z  = (const float*)d_in[0];
    const float* cb = (const float*)d_in[1];
    float* out = (float*)d_out;

    cudaFuncSetAttribute(argmin_mma,
                         cudaFuncAttributeMaxDynamicSharedMemorySize, SM_TOTAL);

    cnorm_kernel   <<<KCODES / 8, 256>>>(cb);
    argmin_mma     <<<M_ROWS / 128, 256, SM_TOTAL>>>(z, cb);
    recheck_kernel <<<64, 256>>>(z, cb);
    gather_kernel  <<<2048, 256>>>(z, cb, out);
    finalize_kernel<<<1, 1024>>>(out);
}

// round 6
// speedup vs baseline: 3.1986x; 1.0904x over previous
#include <cuda_runtime.h>
#include <cuda_bf16.h>
#include <cstdint>

#define M_ROWS   32768
#define DIM      256
#define KCODES   1024
#define MARGIN   0.25f
#define CHECK_CAP 8192

// Scratch (no cudaMalloc allowed)
__device__ int   g_indices[M_ROWS];
__device__ float g_cnorm[KCODES];
__device__ float g_partials[2048];
__device__ int   g_ncheck;
__device__ int4  g_check[CHECK_CAP];

// ---------------------------------------------------------------------------
// SMEM layout (dynamic), fragment-order storage for tf32 mma:
//  A: [m_block 0..7][kstep 0..31][lane 0..31][4 floats]   = 128 KB (full K res)
//  B: 2 bufs x [n_block 0..15][ksl 0..3][lane 0..31][2 floats] = 2 x 16 KB
// ---------------------------------------------------------------------------
#define SM_A     0
#define SM_BF(b) (131072 + (b) * 16384)
#define SM_RED   163840
#define SM_TOTAL 172032

__device__ __forceinline__ uint32_t smem_u32(const void* p) {
    uint32_t a;
    asm("{ .reg .u64 t; cvta.to.shared.u64 t, %1; cvt.u32.u64 %0, t; }"
        : "=r"(a) : "l"(p));
    return a;
}

__device__ __forceinline__ void lds128(uint32_t* r, uint32_t addr) {
    asm volatile("ld.shared.v4.u32 {%0,%1,%2,%3}, [%4];"
                 : "=r"(r[0]), "=r"(r[1]), "=r"(r[2]), "=r"(r[3]) : "r"(addr));
}
__device__ __forceinline__ void lds64(uint32_t* r, uint32_t addr) {
    asm volatile("ld.shared.v2.u32 {%0,%1}, [%2];"
                 : "=r"(r[0]), "=r"(r[1]) : "r"(addr));
}
__device__ __forceinline__ void sts32(uint32_t addr, uint32_t v) {
    asm volatile("st.shared.u32 [%0], %1;" :: "r"(addr), "r"(v) : "memory");
}

// mma.m16n8k8 tf32: A 4 regs, B 2 regs, D 4 fp32 (raw fp32 bits as tf32)
__device__ __forceinline__ void mma_tf32(float* d, const uint32_t* a,
                                         const uint32_t* b) {
    asm volatile(
        "mma.sync.aligned.m16n8k8.row.col.f32.tf32.tf32.f32 "
        "{%0,%1,%2,%3}, {%4,%5,%6,%7}, {%8,%9}, {%0,%1,%2,%3};"
        : "+f"(d[0]), "+f"(d[1]), "+f"(d[2]), "+f"(d[3])
        : "r"(a[0]), "r"(a[1]), "r"(a[2]), "r"(a[3]), "r"(b[0]), "r"(b[1]));
}

__device__ __forceinline__ void upd2(float& m1, int& i1, float& m2, int& i2,
                                     float d, int c) {
    if (d < m1 || (d == m1 && c < i1)) { m2 = m1; i2 = i1; m1 = d; i1 = c; }
    else if (d < m2 || (d == m2 && c < i2)) { m2 = d; i2 = c; }
}
__device__ __forceinline__ void merge2(float& m1, int& i1, float& m2, int& i2,
                                       float om1, int oi1, float om2, int oi2) {
    if (om1 < m1 || (om1 == m1 && oi1 < i1)) {
        float c = m1; int ci = i1;
        m1 = om1; i1 = oi1;
        if (om2 < c || (om2 == c && oi2 < ci)) { m2 = om2; i2 = oi2; }
        else                                   { m2 = c;   i2 = ci;  }
    } else if (om1 < m2 || (om1 == m2 && oi1 < i2)) {
        m2 = om1; i2 = oi1;
    }
}

// ---------------------------------------------------------------------------
// Kernel 1: codebook norms + zero recheck counter
// ---------------------------------------------------------------------------
__global__ void cnorm_kernel(const float* __restrict__ codebook) {
    if (blockIdx.x == 0 && threadIdx.x == 0) g_ncheck = 0;
    int warp = (blockIdx.x * blockDim.x + threadIdx.x) >> 5;
    int lane = threadIdx.x & 31;
    if (warp >= KCODES) return;
    const float* row = codebook + (size_t)warp * DIM;
    float s = 0.f;
    #pragma unroll
    for (int i = 0; i < DIM / 32; ++i) { float v = row[lane + i * 32]; s += v * v; }
    #pragma unroll
    for (int o = 16; o; o >>= 1) s += __shfl_xor_sync(0xffffffffu, s, o);
    if (lane == 0) g_cnorm[warp] = s;
}

// ---------------------------------------------------------------------------
// Kernel 2: single-pass tf32 distance GEMM + fused top-2 argmin.
// Per CTA: 128 rows x 1024 codes, K=256. dist = ||e||^2 - 2*dot.
// tf32 noise ~0.01-0.03 abs; MARGIN=0.25 flags near-ties for exact recheck.
// ---------------------------------------------------------------------------
__global__ __launch_bounds__(256, 1)
void argmin_tf32(const float* __restrict__ z, const float* __restrict__ cb) {
    extern __shared__ char sm[];
    const int tid  = threadIdx.x;
    const int lane = tid & 31;
    const int wid  = tid >> 5;
    const int wm   = wid >> 2;      // 0..1 : M group of 64 rows
    const int wn   = wid & 3;       // 0..3 : N group of 32 codes
    const int q    = lane & 3;
    const int rowBase = blockIdx.x * 128;
    const uint32_t sbase = smem_u32(sm);

    // ---- A prologue: z rows -> fragment-order smem (raw fp32 bits) ----
    // value A[r][c] -> mb=r>>4, kstep=c>>3, lane=(r&7)*4+(c&3),
    //                  frag=((r>>3)&1) + 2*((c>>2)&1)
    #pragma unroll
    for (int it = 0; it < 32; ++it) {
        int idx = it * 256 + tid;          // [0, 8192) float4s
        int r = idx >> 6, c = (idx & 63) * 4;
        float4 v = *(const float4*)(z + (size_t)(rowBase + r) * DIM + c);
        int mb = r >> 4, kstep = c >> 3;
        int fbase = ((r >> 3) & 1) + 2 * ((c >> 2) & 1);
        uint32_t lbase = sbase + SM_A + (uint32_t)((mb * 32 + kstep) * 512
                       + ((r & 7) * 4) * 16 + fbase * 4);
        sts32(lbase +  0, __float_as_uint(v.x));
        sts32(lbase + 16, __float_as_uint(v.y));
        sts32(lbase + 32, __float_as_uint(v.z));
        sts32(lbase + 48, __float_as_uint(v.w));
    }

    float tm1[8], tm2[8];
    int   ti1[8], ti2[8];
    #pragma unroll
    for (int s = 0; s < 8; ++s) {
        tm1[s] = 3.4e38f; tm2[s] = 3.4e38f;
        ti1[s] = 0x7fffffff; ti2[s] = 0x7fffffff;
    }

    for (int chunk = 0; chunk < 8; ++chunk) {
        const int codeBase = chunk * 128;

        float acc[4][4][4];
        #pragma unroll
        for (int mt = 0; mt < 4; ++mt)
            #pragma unroll
            for (int nt = 0; nt < 4; ++nt)
                #pragma unroll
                for (int e = 0; e < 4; ++e) acc[mt][nt][e] = 0.f;

        float cn[4][2];
        #pragma unroll
        for (int nt = 0; nt < 4; ++nt) {
            int c0 = codeBase + wn * 32 + nt * 8 + 2 * q;
            cn[nt][0] = g_cnorm[c0];
            cn[nt][1] = g_cnorm[c0 + 1];
        }

        // produce k-tile 0 into buf 0
        // B[n][k_local] -> nb=n>>3, ksl=(k_local>>3), lane=(n&7)*4+(k&3),
        //                  slot=(k_local>>2)&1
        #pragma unroll
        for (int it = 0; it < 4; ++it) {
            int idx = it * 256 + tid;      // [0, 1024): 128 codes x 8 float4
            int n = idx >> 3, fc = idx & 7;
            float4 v = *(const float4*)(cb + (size_t)(codeBase + n) * DIM + fc * 4);
            int nb = n >> 3, ksl = fc >> 1, hi4 = fc & 1;
            uint32_t lbase = sbase + SM_BF(0) + (uint32_t)(((nb * 4 + ksl) * 32
                           + (n & 7) * 4) * 8 + hi4 * 4);
            sts32(lbase +  0, __float_as_uint(v.x));
            sts32(lbase +  8, __float_as_uint(v.y));
            sts32(lbase + 16, __float_as_uint(v.z));
            sts32(lbase + 24, __float_as_uint(v.w));
        }

        for (int kt = 0; kt < 8; ++kt) {
            __syncthreads();               // buf[kt&1] ready; prev mma drained
            const int buf = kt & 1;

            // stage LDG for next k-tile (overlaps with mma below)
            float4 stg[4];
            if (kt < 7) {
                #pragma unroll
                for (int it = 0; it < 4; ++it) {
                    int idx = it * 256 + tid;
                    int n = idx >> 3, fc = idx & 7;
                    stg[it] = *(const float4*)
                        (cb + (size_t)(codeBase + n) * DIM + (kt + 1) * 32 + fc * 4);
                }
            }

            // mma over buf: 4 ksteps of k8
            #pragma unroll
            for (int ksl = 0; ksl < 4; ++ksl) {
                uint32_t a[4][4], b[4][2];
                #pragma unroll
                for (int mt = 0; mt < 4; ++mt) {
                    int mb = wm * 4 + mt, kstep = kt * 4 + ksl;
                    lds128(a[mt], sbase + SM_A +
                           (uint32_t)((mb * 32 + kstep) * 512 + lane * 16));
                }
                #pragma unroll
                for (int nt = 0; nt < 4; ++nt) {
                    int nb = wn * 4 + nt;
                    lds64(b[nt], sbase + SM_BF(buf) +
                          (uint32_t)(((nb * 4 + ksl) * 32 + lane) * 8));
                }
                #pragma unroll
                for (int mt = 0; mt < 4; ++mt)
                    #pragma unroll
                    for (int nt = 0; nt < 4; ++nt)
                        mma_tf32(acc[mt][nt], a[mt], b[nt]);
            }

            // scatter staged k-tile into the other buffer
            if (kt < 7) {
                #pragma unroll
                for (int it = 0; it < 4; ++it) {
                    int idx = it * 256 + tid;
                    int n = idx >> 3, fc = idx & 7;
                    int nb = n >> 3, ksl = fc >> 1, hi4 = fc & 1;
                    uint32_t lbase = sbase + SM_BF(buf ^ 1) +
                        (uint32_t)(((nb * 4 + ksl) * 32 + (n & 7) * 4) * 8 + hi4 * 4);
                    sts32(lbase +  0, __float_as_uint(stg[it].x));
                    sts32(lbase +  8, __float_as_uint(stg[it].y));
                    sts32(lbase + 16, __float_as_uint(stg[it].z));
                    sts32(lbase + 24, __float_as_uint(stg[it].w));
                }
            }
        }

        // chunk epilogue: dist = cn - 2*dot, per-thread top-2 update
        #pragma unroll
        for (int mt = 0; mt < 4; ++mt)
            #pragma unroll
            for (int nt = 0; nt < 4; ++nt) {
                int col = codeBase + wn * 32 + nt * 8 + 2 * q;
                #pragma unroll
                for (int hh = 0; hh < 2; ++hh) {
                    int s = mt * 2 + hh;
                    float d0 = fmaf(-2.f, acc[mt][nt][hh * 2 + 0], cn[nt][0]);
                    float d1 = fmaf(-2.f, acc[mt][nt][hh * 2 + 1], cn[nt][1]);
                    upd2(tm1[s], ti1[s], tm2[s], ti2[s], d0, col);
                    upd2(tm1[s], ti1[s], tm2[s], ti2[s], d1, col + 1);
                }
            }
    }

    // ---- final reduce: quad shuffle, then across the 4 N-warps via SMEM ----
    float4* red = (float4*)(sm + SM_RED);   // [128 rows][4 wn]
    #pragma unroll
    for (int s = 0; s < 8; ++s) {
        float m1 = tm1[s], m2 = tm2[s];
        int   i1 = ti1[s], i2 = ti2[s];
        #pragma unroll
        for (int off = 1; off <= 2; off <<= 1) {
            float om1 = __shfl_xor_sync(0xffffffffu, m1, off);
            int   oi1 = __shfl_xor_sync(0xffffffffu, i1, off);
            float om2 = __shfl_xor_sync(0xffffffffu, m2, off);
            int   oi2 = __shfl_xor_sync(0xffffffffu, i2, off);
            merge2(m1, i1, m2, i2, om1, oi1, om2, oi2);
        }
        if (q == 0) {
            int mt = s >> 1, hh = s & 1;
            int row = wm * 64 + mt * 16 + hh * 8 + (lane >> 2);
            red[row * 4 + wn] = make_float4(m1, __int_as_float(i1),
                                            m2, __int_as_float(i2));
        }
    }
    __syncthreads();

    if (tid < 128) {
        float4 p = red[tid * 4 + 0];
        float m1 = p.x, m2 = p.z;
        int   i1 = __float_as_int(p.y), i2 = __float_as_int(p.w);
        #pragma unroll
        for (int w = 1; w < 4; ++w) {
            float4 o = red[tid * 4 + w];
            merge2(m1, i1, m2, i2, o.x, __float_as_int(o.y),
                   o.z, __float_as_int(o.w));
        }
        int row = rowBase + tid;
        g_indices[row] = i1;
        if (m2 - m1 <= MARGIN) {
            int slot = atomicAdd(&g_ncheck, 1);
            if (slot < CHECK_CAP) g_check[slot] = make_int4(row, i1, i2, 0);
        }
    }
}

// ---------------------------------------------------------------------------
// Kernel 3: exact fp32 recheck of queued near-tie rows (one warp per entry)
// ---------------------------------------------------------------------------
__global__ void recheck_kernel(const float* __restrict__ z,
                               const float* __restrict__ cb) {
    int nw = (gridDim.x * blockDim.x) >> 5;
    int w = (blockIdx.x * blockDim.x + threadIdx.x) >> 5;
    int lane = threadIdx.x & 31;
    int n = g_ncheck; if (n > CHECK_CAP) n = CHECK_CAP;
    for (int e = w; e < n; e += nw) {
        int4 ent = g_check[e];
        const float* zr = z  + (size_t)ent.x * DIM;
        const float* e1 = cb + (size_t)ent.y * DIM;
        const float* e2 = cb + (size_t)ent.z * DIM;
        float d1 = 0.f, d2 = 0.f;
        for (int i = lane; i < DIM; i += 32) {
            float zv = zr[i];
            float a = zv - e1[i]; d1 += a * a;
            float b = zv - e2[i]; d2 += b * b;
        }
        #pragma unroll
        for (int o = 16; o; o >>= 1) {
            d1 += __shfl_xor_sync(0xffffffffu, d1, o);
            d2 += __shfl_xor_sync(0xffffffffu, d2, o);
        }
        if (lane == 0) {
            int best = (d1 < d2) ? ent.y : ((d2 < d1) ? ent.z
                        : (ent.y < ent.z ? ent.y : ent.z));
            g_indices[ent.x] = best;
        }
    }
}

// ---------------------------------------------------------------------------
// Kernel 4: copy z_e, gather z_q (z_q_st == z_q), partial loss sums
// ---------------------------------------------------------------------------
__global__ void gather_kernel(const float* __restrict__ z,
                              const float* __restrict__ cb,
                              float* __restrict__ out) {
    const int TOTAL4 = (M_ROWS * DIM) / 4;
    float* __restrict__ out_ze = out;
    float* __restrict__ out_zq = out + (size_t)M_ROWS * DIM + 1;

    float lsum = 0.f;
    int stride = gridDim.x * blockDim.x;
    for (int t = blockIdx.x * blockDim.x + threadIdx.x; t < TOTAL4; t += stride) {
        float4 ze = ((const float4*)z)[t];
        ((float4*)out_ze)[t] = ze;
        int row = t >> 6;
        int idx = g_indices[row];
        float4 qv = ((const float4*)cb)[(size_t)idx * 64 + (t & 63)];
        float dx = qv.x - ze.x, dy = qv.y - ze.y;
        float dz = qv.z - ze.z, dw = qv.w - ze.w;
        lsum += dx * dx + dy * dy + dz * dz + dw * dw;
        size_t b = (size_t)t * 4;
        out_zq[b + 0] = qv.x; out_zq[b + 1] = qv.y;
        out_zq[b + 2] = qv.z; out_zq[b + 3] = qv.w;
    }

    __shared__ float red[256];
    red[threadIdx.x] = lsum;
    __syncthreads();
    #pragma unroll
    for (int s = 128; s; s >>= 1) {
        if (threadIdx.x < s) red[threadIdx.x] += red[threadIdx.x + s];
        __syncthreads();
    }
    if (threadIdx.x == 0) g_partials[blockIdx.x] = red[0];
}

// ---------------------------------------------------------------------------
// Kernel 5: deterministic final loss
// ---------------------------------------------------------------------------
__global__ void finalize_kernel(float* __restrict__ out) {
    __shared__ float red[1024];
    int t = threadIdx.x;
    red[t] = g_partials[t] + g_partials[t + 1024];
    __syncthreads();
    #pragma unroll
    for (int s = 512; s; s >>= 1) {
        if (t < s) red[t] += red[t + s];
        __syncthreads();
    }
    if (t == 0)
        out[(size_t)M_ROWS * DIM] = 2.0f * red[0] / (float)(M_ROWS * DIM);
}

// ---------------------------------------------------------------------------
extern "C" void kernel_launch(void* const* d_in, const int* in_sizes, int n_in,
                              void* d_out, int out_size) {
    const float* z  = (const float*)d_in[0];
    const float* cb = (const float*)d_in[1];
    float* out = (float*)d_out;

    cudaFuncSetAttribute(argmin_tf32,
                         cudaFuncAttributeMaxDynamicSharedMemorySize, SM_TOTAL);

    cnorm_kernel   <<<KCODES / 8, 256>>>(cb);
    argmin_tf32    <<<M_ROWS / 128, 256, SM_TOTAL>>>(z, cb);
    recheck_kernel <<<64, 256>>>(z, cb);
    gather_kernel  <<<2048, 256>>>(z, cb, out);
    finalize_kernel<<<1, 1024>>>(out);
}

// round 7
// speedup vs baseline: 4.0046x; 1.2520x over previous
#include <cuda_runtime.h>
#include <cuda_bf16.h>
#include <cstdint>

#define M_ROWS   32768
#define DIM      256
#define KCODES   1024
#define MARGIN   0.25f
#define CHECK_CAP 8192

// Scratch (no cudaMalloc allowed)
__device__ int   g_indices[M_ROWS];
__device__ float g_cnorm[KCODES];
__device__ float g_partials[2048];
__device__ int   g_ncheck;
__device__ int4  g_check[CHECK_CAP];

// ---------------------------------------------------------------------------
// SMEM layout (dynamic), per CTA (64 rows):
//  A: fragment-order [mb 0..3][kstep 0..31][lane 0..31][4 floats] = 64 KB
//  B: 2 bufs x swizzled raw [128 codes][32 k fp32]                = 2 x 16 KB
//  red: [64 rows][4] float4                                       = 4 KB
// ---------------------------------------------------------------------------
#define SM_A     0
#define SM_BF(b) (65536 + (b) * 16384)
#define SM_RED   98304
#define SM_TOTAL 102400

__device__ __forceinline__ uint32_t smem_u32(const void* p) {
    uint32_t a;
    asm("{ .reg .u64 t; cvta.to.shared.u64 t, %1; cvt.u32.u64 %0, t; }"
        : "=r"(a) : "l"(p));
    return a;
}
__device__ __forceinline__ void lds128(uint32_t* r, uint32_t addr) {
    asm volatile("ld.shared.v4.u32 {%0,%1,%2,%3}, [%4];"
                 : "=r"(r[0]), "=r"(r[1]), "=r"(r[2]), "=r"(r[3]) : "r"(addr));
}
__device__ __forceinline__ uint32_t lds32(uint32_t addr) {
    uint32_t v;
    asm volatile("ld.shared.u32 %0, [%1];" : "=r"(v) : "r"(addr));
    return v;
}
__device__ __forceinline__ void sts32(uint32_t addr, uint32_t v) {
    asm volatile("st.shared.u32 [%0], %1;" :: "r"(addr), "r"(v) : "memory");
}
__device__ __forceinline__ void cp16(uint32_t dst, const void* src) {
    asm volatile("cp.async.cg.shared.global [%0], [%1], 16;"
                 :: "r"(dst), "l"(src) : "memory");
}
__device__ __forceinline__ void cp_commit() {
    asm volatile("cp.async.commit_group;" ::: "memory");
}
__device__ __forceinline__ void cp_wait_all() {
    asm volatile("cp.async.wait_group 0;" ::: "memory");
}

// mma.m16n8k8 tf32 (raw fp32 bits as tf32 operands)
__device__ __forceinline__ void mma_tf32(float* d, const uint32_t* a,
                                         const uint32_t* b) {
    asm volatile(
        "mma.sync.aligned.m16n8k8.row.col.f32.tf32.tf32.f32 "
        "{%0,%1,%2,%3}, {%4,%5,%6,%7}, {%8,%9}, {%0,%1,%2,%3};"
        : "+f"(d[0]), "+f"(d[1]), "+f"(d[2]), "+f"(d[3])
        : "r"(a[0]), "r"(a[1]), "r"(a[2]), "r"(a[3]), "r"(b[0]), "r"(b[1]));
}

__device__ __forceinline__ void upd2(float& m1, int& i1, float& m2, int& i2,
                                     float d, int c) {
    if (d < m1 || (d == m1 && c < i1)) { m2 = m1; i2 = i1; m1 = d; i1 = c; }
    else if (d < m2 || (d == m2 && c < i2)) { m2 = d; i2 = c; }
}
__device__ __forceinline__ void merge2(float& m1, int& i1, float& m2, int& i2,
                                       float om1, int oi1, float om2, int oi2) {
    if (om1 < m1 || (om1 == m1 && oi1 < i1)) {
        float c = m1; int ci = i1;
        m1 = om1; i1 = oi1;
        if (om2 < c || (om2 == c && oi2 < ci)) { m2 = om2; i2 = oi2; }
        else                                   { m2 = c;   i2 = ci;  }
    } else if (om1 < m2 || (om1 == m2 && oi1 < i2)) {
        m2 = om1; i2 = oi1;
    }
}

// ---------------------------------------------------------------------------
// Kernel 1: codebook norms + zero recheck counter
// ---------------------------------------------------------------------------
__global__ void cnorm_kernel(const float* __restrict__ codebook) {
    if (blockIdx.x == 0 && threadIdx.x == 0) g_ncheck = 0;
    int warp = (blockIdx.x * blockDim.x + threadIdx.x) >> 5;
    int lane = threadIdx.x & 31;
    if (warp >= KCODES) return;
    const float* row = codebook + (size_t)warp * DIM;
    float s = 0.f;
    #pragma unroll
    for (int i = 0; i < DIM / 32; ++i) { float v = row[lane + i * 32]; s += v * v; }
    #pragma unroll
    for (int o = 16; o; o >>= 1) s += __shfl_xor_sync(0xffffffffu, s, o);
    if (lane == 0) g_cnorm[warp] = s;
}

// ---------------------------------------------------------------------------
// Kernel 2: tf32 distance GEMM + fused top-2 argmin.
// Per CTA: 64 rows x 1024 codes, K=256. 2 CTAs/SM. B streamed via cp.async.
// ---------------------------------------------------------------------------
__global__ __launch_bounds__(256, 2)
void argmin_tf32(const float* __restrict__ z, const float* __restrict__ cb) {
    extern __shared__ char sm[];
    const int tid  = threadIdx.x;
    const int lane = tid & 31;
    const int wid  = tid >> 5;
    const int wm   = wid >> 2;      // 0..1 : M group of 32 rows
    const int wn   = wid & 3;       // 0..3 : N group of 32 codes
    const int q    = lane & 3;
    const int rowBase = blockIdx.x * 64;
    const uint32_t sbase = smem_u32(sm);

    // cp.async dst indices for this thread (4 chunks of 16B per tile)
    // element (n, k_local): dst word = n*32 + (k ^ ((n&7)<<2))
    uint32_t cpd[4];
    int      cpn[4], cpc[4];
    #pragma unroll
    for (int it = 0; it < 4; ++it) {
        int idx = it * 256 + tid;          // [0, 1024): 128 codes x 8 chunks
        int n = idx >> 3, c = idx & 7;
        cpn[it] = n; cpc[it] = c * 4;
        cpd[it] = (uint32_t)(n * 128 + 16 * (c ^ (n & 7)));
    }

    // prefetch tile 0 (chunk 0, kt 0)
    #pragma unroll
    for (int it = 0; it < 4; ++it)
        cp16(sbase + SM_BF(0) + cpd[it],
             cb + (size_t)cpn[it] * DIM + cpc[it]);
    cp_commit();

    // ---- A prologue: 64 z rows -> fragment-order smem (raw fp32 bits) ----
    #pragma unroll
    for (int it = 0; it < 16; ++it) {
        int idx = it * 256 + tid;          // [0, 4096) float4s
        int r = idx >> 6, c = (idx & 63) * 4;
        float4 v = *(const float4*)(z + (size_t)(rowBase + r) * DIM + c);
        int mb = r >> 4, kstep = c >> 3;
        int fbase = ((r >> 3) & 1) + 2 * ((c >> 2) & 1);
        uint32_t lbase = sbase + SM_A + (uint32_t)((mb * 32 + kstep) * 512
                       + ((r & 7) * 4) * 16 + fbase * 4);
        sts32(lbase +  0, __float_as_uint(v.x));
        sts32(lbase + 16, __float_as_uint(v.y));
        sts32(lbase + 32, __float_as_uint(v.z));
        sts32(lbase + 48, __float_as_uint(v.w));
    }

    float tm1[4], tm2[4];
    int   ti1[4], ti2[4];
    #pragma unroll
    for (int s = 0; s < 4; ++s) {
        tm1[s] = 3.4e38f; tm2[s] = 3.4e38f;
        ti1[s] = 0x7fffffff; ti2[s] = 0x7fffffff;
    }

    float acc[2][4][4];
    #pragma unroll
    for (int mt = 0; mt < 2; ++mt)
        #pragma unroll
        for (int nt = 0; nt < 4; ++nt)
            #pragma unroll
            for (int e = 0; e < 4; ++e) acc[mt][nt][e] = 0.f;

    #pragma unroll 1
    for (int t = 0; t < 64; ++t) {         // 8 chunks x 8 k-tiles
        const int buf = t & 1;

        cp_wait_all();                      // tile t resident
        __syncthreads();

        // issue prefetch of tile t+1 (overlaps mma below)
        if (t < 63) {
            int tn = t + 1;
            const float* src0 = cb + (size_t)(tn >> 3) * 128 * DIM + (tn & 7) * 32;
            #pragma unroll
            for (int it = 0; it < 4; ++it)
                cp16(sbase + SM_BF(buf ^ 1) + cpd[it],
                     src0 + (size_t)cpn[it] * DIM + cpc[it]);
            cp_commit();
        }

        // mma over tile t: 4 k-steps of k8
        const int kt = t & 7;
        #pragma unroll
        for (int ksl = 0; ksl < 4; ++ksl) {
            uint32_t a[2][4], b[4][2];
            #pragma unroll
            for (int mt = 0; mt < 2; ++mt) {
                int mb = wm * 2 + mt, kstep = kt * 4 + ksl;
                lds128(a[mt], sbase + SM_A +
                       (uint32_t)((mb * 32 + kstep) * 512 + lane * 16));
            }
            #pragma unroll
            for (int nt = 0; nt < 4; ++nt) {
                int n = (wn * 4 + nt) * 8 + (lane >> 2);
                int k0 = ksl * 8 + (lane & 3);
                uint32_t base = sbase + SM_BF(buf) + (uint32_t)(n * 128);
                b[nt][0] = lds32(base + (uint32_t)((k0      ^ ((n & 7) << 2)) * 4));
                b[nt][1] = lds32(base + (uint32_t)(((k0 + 4) ^ ((n & 7) << 2)) * 4));
            }
            #pragma unroll
            for (int mt = 0; mt < 2; ++mt)
                #pragma unroll
                for (int nt = 0; nt < 4; ++nt)
                    mma_tf32(acc[mt][nt], a[mt], b[nt]);
        }

        // chunk epilogue every 8 tiles
        if ((t & 7) == 7) {
            const int codeBase = (t >> 3) * 128;
            #pragma unroll
            for (int mt = 0; mt < 2; ++mt)
                #pragma unroll
                for (int nt = 0; nt < 4; ++nt) {
                    int col = codeBase + wn * 32 + nt * 8 + 2 * q;
                    float c0 = g_cnorm[col], c1 = g_cnorm[col + 1];
                    #pragma unroll
                    for (int hh = 0; hh < 2; ++hh) {
                        int s = mt * 2 + hh;
                        float d0 = fmaf(-2.f, acc[mt][nt][hh * 2 + 0], c0);
                        float d1 = fmaf(-2.f, acc[mt][nt][hh * 2 + 1], c1);
                        upd2(tm1[s], ti1[s], tm2[s], ti2[s], d0, col);
                        upd2(tm1[s], ti1[s], tm2[s], ti2[s], d1, col + 1);
                    }
                }
            #pragma unroll
            for (int mt = 0; mt < 2; ++mt)
                #pragma unroll
                for (int nt = 0; nt < 4; ++nt)
                    #pragma unroll
                    for (int e = 0; e < 4; ++e) acc[mt][nt][e] = 0.f;
        }
    }

    // ---- final reduce: quad shuffle, then across the 4 N-warps via SMEM ----
    float4* red = (float4*)(sm + SM_RED);   // [64 rows][4 wn]
    __syncthreads();
    #pragma unroll
    for (int s = 0; s < 4; ++s) {
        float m1 = tm1[s], m2 = tm2[s];
        int   i1 = ti1[s], i2 = ti2[s];
        #pragma unroll
        for (int off = 1; off <= 2; off <<= 1) {
            float om1 = __shfl_xor_sync(0xffffffffu, m1, off);
            int   oi1 = __shfl_xor_sync(0xffffffffu, i1, off);
            float om2 = __shfl_xor_sync(0xffffffffu, m2, off);
            int   oi2 = __shfl_xor_sync(0xffffffffu, i2, off);
            merge2(m1, i1, m2, i2, om1, oi1, om2, oi2);
        }
        if (q == 0) {
            int mt = s >> 1, hh = s & 1;
            int row = wm * 32 + mt * 16 + hh * 8 + (lane >> 2);
            red[row * 4 + wn] = make_float4(m1, __int_as_float(i1),
                                            m2, __int_as_float(i2));
        }
    }
    __syncthreads();

    if (tid < 64) {
        float4 p = red[tid * 4 + 0];
        float m1 = p.x, m2 = p.z;
        int   i1 = __float_as_int(p.y), i2 = __float_as_int(p.w);
        #pragma unroll
        for (int w = 1; w < 4; ++w) {
            float4 o = red[tid * 4 + w];
            merge2(m1, i1, m2, i2, o.x, __float_as_int(o.y),
                   o.z, __float_as_int(o.w));
        }
        int row = rowBase + tid;
        g_indices[row] = i1;
        if (m2 - m1 <= MARGIN) {
            int slot = atomicAdd(&g_ncheck, 1);
            if (slot < CHECK_CAP) g_check[slot] = make_int4(row, i1, i2, 0);
        }
    }
}

// ---------------------------------------------------------------------------
// Kernel 3: exact fp32 recheck of queued near-tie rows (one warp per entry)
// ---------------------------------------------------------------------------
__global__ void recheck_kernel(const float* __restrict__ z,
                               const float* __restrict__ cb) {
    int nw = (gridDim.x * blockDim.x) >> 5;
    int w = (blockIdx.x * blockDim.x + threadIdx.x) >> 5;
    int lane = threadIdx.x & 31;
    int n = g_ncheck; if (n > CHECK_CAP) n = CHECK_CAP;
    for (int e = w; e < n; e += nw) {
        int4 ent = g_check[e];
        const float* zr = z  + (size_t)ent.x * DIM;
        const float* e1 = cb + (size_t)ent.y * DIM;
        const float* e2 = cb + (size_t)ent.z * DIM;
        float d1 = 0.f, d2 = 0.f;
        for (int i = lane; i < DIM; i += 32) {
            float zv = zr[i];
            float a = zv - e1[i]; d1 += a * a;
            float b = zv - e2[i]; d2 += b * b;
        }
        #pragma unroll
        for (int o = 16; o; o >>= 1) {
            d1 += __shfl_xor_sync(0xffffffffu, d1, o);
            d2 += __shfl_xor_sync(0xffffffffu, d2, o);
        }
        if (lane == 0) {
            int best = (d1 < d2) ? ent.y : ((d2 < d1) ? ent.z
                        : (ent.y < ent.z ? ent.y : ent.z));
            g_indices[ent.x] = best;
        }
    }
}

// ---------------------------------------------------------------------------
// Kernel 4: copy z_e, gather z_q (z_q_st == z_q), partial loss sums
// ---------------------------------------------------------------------------
__global__ void gather_kernel(const float* __restrict__ z,
                              const float* __restrict__ cb,
                              float* __restrict__ out) {
    const int TOTAL4 = (M_ROWS * DIM) / 4;
    float* __restrict__ out_ze = out;
    float* __restrict__ out_zq = out + (size_t)M_ROWS * DIM + 1;

    float lsum = 0.f;
    int stride = gridDim.x * blockDim.x;
    for (int t = blockIdx.x * blockDim.x + threadIdx.x; t < TOTAL4; t += stride) {
        float4 ze = ((const float4*)z)[t];
        ((float4*)out_ze)[t] = ze;
        int row = t >> 6;
        int idx = g_indices[row];
        float4 qv = ((const float4*)cb)[(size_t)idx * 64 + (t & 63)];
        float dx = qv.x - ze.x, dy = qv.y - ze.y;
        float dz = qv.z - ze.z, dw = qv.w - ze.w;
        lsum += dx * dx + dy * dy + dz * dz + dw * dw;
        size_t b = (size_t)t * 4;
        out_zq[b + 0] = qv.x; out_zq[b + 1] = qv.y;
        out_zq[b + 2] = qv.z; out_zq[b + 3] = qv.w;
    }

    __shared__ float red[256];
    red[threadIdx.x] = lsum;
    __syncthreads();
    #pragma unroll
    for (int s = 128; s; s >>= 1) {
        if (threadIdx.x < s) red[threadIdx.x] += red[threadIdx.x + s];
        __syncthreads();
    }
    if (threadIdx.x == 0) g_partials[blockIdx.x] = red[0];
}

// ---------------------------------------------------------------------------
// Kernel 5: deterministic final loss
// ---------------------------------------------------------------------------
__global__ void finalize_kernel(float* __restrict__ out) {
    __shared__ float red[1024];
    int t = threadIdx.x;
    red[t] = g_partials[t] + g_partials[t + 1024];
    __syncthreads();
    #pragma unroll
    for (int s = 512; s; s >>= 1) {
        if (t < s) red[t] += red[t + s];
        __syncthreads();
    }
    if (t == 0)
        out[(size_t)M_ROWS * DIM] = 2.0f * red[0] / (float)(M_ROWS * DIM);
}

// ---------------------------------------------------------------------------
extern "C" void kernel_launch(void* const* d_in, const int* in_sizes, int n_in,
                              void* d_out, int out_size) {
    const float* z  = (const float*)d_in[0];
    const float* cb = (const float*)d_in[1];
    float* out = (float*)d_out;

    cudaFuncSetAttribute(argmin_tf32,
                         cudaFuncAttributeMaxDynamicSharedMemorySize, SM_TOTAL);

    cnorm_kernel   <<<KCODES / 8, 256>>>(cb);
    argmin_tf32    <<<M_ROWS / 64, 256, SM_TOTAL>>>(z, cb);
    recheck_kernel <<<64, 256>>>(z, cb);
    gather_kernel  <<<2048, 256>>>(z, cb, out);
    finalize_kernel<<<1, 1024>>>(out);
}

// round 8
// speedup vs baseline: 4.1461x; 1.0353x over previous
#include <cuda_runtime.h>
#include <cuda_bf16.h>
#include <cstdint>

#define M_ROWS   32768
#define DIM      256
#define KCODES   1024
#define MARGIN   0.25f
#define CHECK_CAP 8192

// Scratch (no cudaMalloc allowed)
__device__ int   g_indices[M_ROWS];
__device__ float g_cnorm[KCODES];
__device__ float g_partials[2048];
__device__ int   g_ncheck;
__device__ int4  g_check[CHECK_CAP];
// Prepacked codebook in mma B-fragment order:
// [pair p 0..63][ks 0..31][lane 0..31][4 words: nb=2p {b0,b1}, nb=2p+1 {b0,b1}]
// b0 = B[n][k], b1 = B[n][k+4], n = nb*8 + (lane>>2), k = ks*8 + (lane&3)
__device__ float4 g_bfrag[65536];   // 1 MB

// ---------------------------------------------------------------------------
// SMEM layout per CTA (64 rows):
//  A: fragment-order [mb 0..3][kstep 0..31][lane 0..31][4 floats] = 64 KB
//  B: 2 bufs x fragment-order tile [pl 0..7][ka 0..3][lane][4w]   = 2 x 16 KB
//  red: [64 rows][4] float4                                       = 4 KB
// ---------------------------------------------------------------------------
#define SM_A     0
#define SM_BF(b) (65536 + (b) * 16384)
#define SM_RED   98304
#define SM_TOTAL 102400

__device__ __forceinline__ uint32_t smem_u32(const void* p) {
    uint32_t a;
    asm("{ .reg .u64 t; cvta.to.shared.u64 t, %1; cvt.u32.u64 %0, t; }"
        : "=r"(a) : "l"(p));
    return a;
}
__device__ __forceinline__ void lds128(uint32_t* r, uint32_t addr) {
    asm volatile("ld.shared.v4.u32 {%0,%1,%2,%3}, [%4];"
                 : "=r"(r[0]), "=r"(r[1]), "=r"(r[2]), "=r"(r[3]) : "r"(addr));
}
__device__ __forceinline__ void sts32(uint32_t addr, uint32_t v) {
    asm volatile("st.shared.u32 [%0], %1;" :: "r"(addr), "r"(v) : "memory");
}
__device__ __forceinline__ void cp16(uint32_t dst, const void* src) {
    asm volatile("cp.async.cg.shared.global [%0], [%1], 16;"
                 :: "r"(dst), "l"(src) : "memory");
}
__device__ __forceinline__ void cp_commit() {
    asm volatile("cp.async.commit_group;" ::: "memory");
}
__device__ __forceinline__ void cp_wait_all() {
    asm volatile("cp.async.wait_group 0;" ::: "memory");
}

// mma.m16n8k8 tf32 (raw fp32 bits as tf32 operands)
__device__ __forceinline__ void mma_tf32(float* d, const uint32_t* a,
                                         const uint32_t* b) {
    asm volatile(
        "mma.sync.aligned.m16n8k8.row.col.f32.tf32.tf32.f32 "
        "{%0,%1,%2,%3}, {%4,%5,%6,%7}, {%8,%9}, {%0,%1,%2,%3};"
        : "+f"(d[0]), "+f"(d[1]), "+f"(d[2]), "+f"(d[3])
        : "r"(a[0]), "r"(a[1]), "r"(a[2]), "r"(a[3]), "r"(b[0]), "r"(b[1]));
}

__device__ __forceinline__ void upd2(float& m1, int& i1, float& m2, int& i2,
                                     float d, int c) {
    if (d < m1 || (d == m1 && c < i1)) { m2 = m1; i2 = i1; m1 = d; i1 = c; }
    else if (d < m2 || (d == m2 && c < i2)) { m2 = d; i2 = c; }
}
__device__ __forceinline__ void merge2(float& m1, int& i1, float& m2, int& i2,
                                       float om1, int oi1, float om2, int oi2) {
    if (om1 < m1 || (om1 == m1 && oi1 < i1)) {
        float c = m1; int ci = i1;
        m1 = om1; i1 = oi1;
        if (om2 < c || (om2 == c && oi2 < ci)) { m2 = om2; i2 = oi2; }
        else                                   { m2 = c;   i2 = ci;  }
    } else if (om1 < m2 || (om1 == m2 && oi1 < i2)) {
        m2 = om1; i2 = oi1;
    }
}

// ---------------------------------------------------------------------------
// Kernel 0: prepack codebook into B-fragment order (one shot, ~1MB)
// ---------------------------------------------------------------------------
__global__ void prepack_kernel(const float* __restrict__ cb) {
    int idx = blockIdx.x * 256 + threadIdx.x;   // (p*32 + ks)*32 + lane
    int lane = idx & 31;
    int ks   = (idx >> 5) & 31;
    int p    = idx >> 10;                       // 0..63
    int k  = ks * 8 + (lane & 3);
    int n0 = (2 * p) * 8 + (lane >> 2);
    int n1 = n0 + 8;
    float4 v;
    v.x = cb[(size_t)n0 * DIM + k];
    v.y = cb[(size_t)n0 * DIM + k + 4];
    v.z = cb[(size_t)n1 * DIM + k];
    v.w = cb[(size_t)n1 * DIM + k + 4];
    g_bfrag[idx] = v;
}

// ---------------------------------------------------------------------------
// Kernel 1: codebook norms + zero recheck counter
// ---------------------------------------------------------------------------
__global__ void cnorm_kernel(const float* __restrict__ codebook) {
    if (blockIdx.x == 0 && threadIdx.x == 0) g_ncheck = 0;
    int warp = (blockIdx.x * blockDim.x + threadIdx.x) >> 5;
    int lane = threadIdx.x & 31;
    if (warp >= KCODES) return;
    const float* row = codebook + (size_t)warp * DIM;
    float s = 0.f;
    #pragma unroll
    for (int i = 0; i < DIM / 32; ++i) { float v = row[lane + i * 32]; s += v * v; }
    #pragma unroll
    for (int o = 16; o; o >>= 1) s += __shfl_xor_sync(0xffffffffu, s, o);
    if (lane == 0) g_cnorm[warp] = s;
}

// ---------------------------------------------------------------------------
// Kernel 2: tf32 distance GEMM + fused top-2 argmin.
// Per CTA: 64 rows x 1024 codes, K=256. 2 CTAs/SM. B streamed via cp.async
// from the prepacked fragment-order buffer (zero repack in the loop).
// ---------------------------------------------------------------------------
__global__ __launch_bounds__(256, 2)
void argmin_tf32(const float* __restrict__ z, const float* __restrict__ cb) {
    extern __shared__ char sm[];
    const int tid  = threadIdx.x;
    const int lane = tid & 31;
    const int wid  = tid >> 5;
    const int wm   = wid >> 2;      // 0..1 : M group of 32 rows
    const int wn   = wid & 3;       // 0..3 : N group of 32 codes
    const int q    = lane & 3;
    const int rowBase = blockIdx.x * 64;
    const uint32_t sbase = smem_u32(sm);
    const char* bsrc = (const char*)g_bfrag;

    // cp.async: thread's 4 chunks; dst offset == idx*16 (consumer order),
    // src offset = thread-const + tile base (tile = 8 pairs x 4 ks x 32 lanes)
    uint32_t cpd[4], cps[4];
    #pragma unroll
    for (int it = 0; it < 4; ++it) {
        int idx = it * 256 + tid;              // (pl*4 + ka)*32 + lane
        cpd[it] = (uint32_t)idx * 16;
        int pl = idx >> 7, ka = (idx >> 5) & 3, ls = idx & 31;
        cps[it] = (uint32_t)((pl * 32 + ka) * 512 + ls * 16);
    }

    // prefetch tile 0
    #pragma unroll
    for (int it = 0; it < 4; ++it)
        cp16(sbase + SM_BF(0) + cpd[it], bsrc + cps[it]);
    cp_commit();

    // ---- A prologue: 64 z rows -> fragment-order smem (raw fp32 bits) ----
    #pragma unroll
    for (int it = 0; it < 16; ++it) {
        int idx = it * 256 + tid;              // [0, 4096) float4s
        int r = idx >> 6, c = (idx & 63) * 4;
        float4 v = *(const float4*)(z + (size_t)(rowBase + r) * DIM + c);
        int mb = r >> 4, kstep = c >> 3;
        int fbase = ((r >> 3) & 1) + 2 * ((c >> 2) & 1);
        uint32_t lbase = sbase + SM_A + (uint32_t)((mb * 32 + kstep) * 512
                       + ((r & 7) * 4) * 16 + fbase * 4);
        sts32(lbase +  0, __float_as_uint(v.x));
        sts32(lbase + 16, __float_as_uint(v.y));
        sts32(lbase + 32, __float_as_uint(v.z));
        sts32(lbase + 48, __float_as_uint(v.w));
    }

    float tm1[4], tm2[4];
    int   ti1[4], ti2[4];
    #pragma unroll
    for (int s = 0; s < 4; ++s) {
        tm1[s] = 3.4e38f; tm2[s] = 3.4e38f;
        ti1[s] = 0x7fffffff; ti2[s] = 0x7fffffff;
    }

    float acc[2][4][4];
    #pragma unroll
    for (int mt = 0; mt < 2; ++mt)
        #pragma unroll
        for (int nt = 0; nt < 4; ++nt)
            #pragma unroll
            for (int e = 0; e < 4; ++e) acc[mt][nt][e] = 0.f;

    #pragma unroll 1
    for (int t = 0; t < 64; ++t) {             // 8 chunks x 8 k-tiles
        const int buf = t & 1;

        cp_wait_all();                          // tile t resident
        __syncthreads();

        // issue prefetch of tile t+1 (overlaps mma below)
        if (t < 63) {
            int tn = t + 1;
            uint32_t tbase = (uint32_t)(((tn >> 3) * 256 + (tn & 7) * 4) * 512);
            #pragma unroll
            for (int it = 0; it < 4; ++it)
                cp16(sbase + SM_BF(buf ^ 1) + cpd[it], bsrc + tbase + cps[it]);
            cp_commit();
        }

        // mma over tile t: 4 k-steps of k8
        const int kt = t & 7;
        #pragma unroll
        for (int ksl = 0; ksl < 4; ++ksl) {
            uint32_t a[2][4], bq[2][4];
            #pragma unroll
            for (int mt = 0; mt < 2; ++mt) {
                int mb = wm * 2 + mt, kstep = kt * 4 + ksl;
                lds128(a[mt], sbase + SM_A +
                       (uint32_t)((mb * 32 + kstep) * 512 + lane * 16));
            }
            #pragma unroll
            for (int pp = 0; pp < 2; ++pp) {
                int pl = wn * 2 + pp;
                lds128(bq[pp], sbase + SM_BF(buf) +
                       (uint32_t)(((pl * 4 + ksl) * 32 + lane) * 16));
            }
            #pragma unroll
            for (int mt = 0; mt < 2; ++mt)
                #pragma unroll
                for (int pp = 0; pp < 2; ++pp) {
                    mma_tf32(acc[mt][pp * 2 + 0], a[mt], &bq[pp][0]);
                    mma_tf32(acc[mt][pp * 2 + 1], a[mt], &bq[pp][2]);
                }
        }

        // chunk epilogue every 8 tiles
        if ((t & 7) == 7) {
            const int codeBase = (t >> 3) * 128;
            #pragma unroll
            for (int mt = 0; mt < 2; ++mt)
                #pragma unroll
                for (int nt = 0; nt < 4; ++nt) {
                    int col = codeBase + wn * 32 + nt * 8 + 2 * q;
                    float c0 = g_cnorm[col], c1 = g_cnorm[col + 1];
                    #pragma unroll
                    for (int hh = 0; hh < 2; ++hh) {
                        int s = mt * 2 + hh;
                        float d0 = fmaf(-2.f, acc[mt][nt][hh * 2 + 0], c0);
                        float d1 = fmaf(-2.f, acc[mt][nt][hh * 2 + 1], c1);
                        upd2(tm1[s], ti1[s], tm2[s], ti2[s], d0, col);
                        upd2(tm1[s], ti1[s], tm2[s], ti2[s], d1, col + 1);
                    }
                }
            #pragma unroll
            for (int mt = 0; mt < 2; ++mt)
                #pragma unroll
                for (int nt = 0; nt < 4; ++nt)
                    #pragma unroll
                    for (int e = 0; e < 4; ++e) acc[mt][nt][e] = 0.f;
        }
    }

    // ---- final reduce: quad shuffle, then across the 4 N-warps via SMEM ----
    float4* red = (float4*)(sm + SM_RED);   // [64 rows][4 wn]
    __syncthreads();
    #pragma unroll
    for (int s = 0; s < 4; ++s) {
        float m1 = tm1[s], m2 = tm2[s];
        int   i1 = ti1[s], i2 = ti2[s];
        #pragma unroll
        for (int off = 1; off <= 2; off <<= 1) {
            float om1 = __shfl_xor_sync(0xffffffffu, m1, off);
            int   oi1 = __shfl_xor_sync(0xffffffffu, i1, off);
            float om2 = __shfl_xor_sync(0xffffffffu, m2, off);
            int   oi2 = __shfl_xor_sync(0xffffffffu, i2, off);
            merge2(m1, i1, m2, i2, om1, oi1, om2, oi2);
        }
        if (q == 0) {
            int mt = s >> 1, hh = s & 1;
            int row = wm * 32 + mt * 16 + hh * 8 + (lane >> 2);
            red[row * 4 + wn] = make_float4(m1, __int_as_float(i1),
                                            m2, __int_as_float(i2));
        }
    }
    __syncthreads();

    if (tid < 64) {
        float4 p = red[tid * 4 + 0];
        float m1 = p.x, m2 = p.z;
        int   i1 = __float_as_int(p.y), i2 = __float_as_int(p.w);
        #pragma unroll
        for (int w = 1; w < 4; ++w) {
            float4 o = red[tid * 4 + w];
            merge2(m1, i1, m2, i2, o.x, __float_as_int(o.y),
                   o.z, __float_as_int(o.w));
        }
        int row = rowBase + tid;
        g_indices[row] = i1;
        if (m2 - m1 <= MARGIN) {
            int slot = atomicAdd(&g_ncheck, 1);
            if (slot < CHECK_CAP) g_check[slot] = make_int4(row, i1, i2, 0);
        }
    }
}

// ---------------------------------------------------------------------------
// Kernel 3: exact fp32 recheck of queued near-tie rows (one warp per entry)
// ---------------------------------------------------------------------------
__global__ void recheck_kernel(const float* __restrict__ z,
                               const float* __restrict__ cb) {
    int nw = (gridDim.x * blockDim.x) >> 5;
    int w = (blockIdx.x * blockDim.x + threadIdx.x) >> 5;
    int lane = threadIdx.x & 31;
    int n = g_ncheck; if (n > CHECK_CAP) n = CHECK_CAP;
    for (int e = w; e < n; e += nw) {
        int4 ent = g_check[e];
        const float* zr = z  + (size_t)ent.x * DIM;
        const float* e1 = cb + (size_t)ent.y * DIM;
        const float* e2 = cb + (size_t)ent.z * DIM;
        float d1 = 0.f, d2 = 0.f;
        for (int i = lane; i < DIM; i += 32) {
            float zv = zr[i];
            float a = zv - e1[i]; d1 += a * a;
            float b = zv - e2[i]; d2 += b * b;
        }
        #pragma unroll
        for (int o = 16; o; o >>= 1) {
            d1 += __shfl_xor_sync(0xffffffffu, d1, o);
            d2 += __shfl_xor_sync(0xffffffffu, d2, o);
        }
        if (lane == 0) {
            int best = (d1 < d2) ? ent.y : ((d2 < d1) ? ent.z
                        : (ent.y < ent.z ? ent.y : ent.z));
            g_indices[ent.x] = best;
        }
    }
}

// ---------------------------------------------------------------------------
// Kernel 4: copy z_e, gather z_q (z_q_st == z_q), partial loss sums
// ---------------------------------------------------------------------------
__global__ void gather_kernel(const float* __restrict__ z,
                              const float* __restrict__ cb,
                              float* __restrict__ out) {
    const int TOTAL4 = (M_ROWS * DIM) / 4;
    float* __restrict__ out_ze = out;
    float* __restrict__ out_zq = out + (size_t)M_ROWS * DIM + 1;

    float lsum = 0.f;
    int stride = gridDim.x * blockDim.x;
    for (int t = blockIdx.x * blockDim.x + threadIdx.x; t < TOTAL4; t += stride) {
        float4 ze = ((const float4*)z)[t];
        ((float4*)out_ze)[t] = ze;
        int row = t >> 6;
        int idx = g_indices[row];
        float4 qv = ((const float4*)cb)[(size_t)idx * 64 + (t & 63)];
        float dx = qv.x - ze.x, dy = qv.y - ze.y;
        float dz = qv.z - ze.z, dw = qv.w - ze.w;
        lsum += dx * dx + dy * dy + dz * dz + dw * dw;
        size_t b = (size_t)t * 4;
        out_zq[b + 0] = qv.x; out_zq[b + 1] = qv.y;
        out_zq[b + 2] = qv.z; out_zq[b + 3] = qv.w;
    }

    __shared__ float red[256];
    red[threadIdx.x] = lsum;
    __syncthreads();
    #pragma unroll
    for (int s = 128; s; s >>= 1) {
        if (threadIdx.x < s) red[threadIdx.x] += red[threadIdx.x + s];
        __syncthreads();
    }
    if (threadIdx.x == 0) g_partials[blockIdx.x] = red[0];
}

// ---------------------------------------------------------------------------
// Kernel 5: deterministic final loss
// ---------------------------------------------------------------------------
__global__ void finalize_kernel(float* __restrict__ out) {
    __shared__ float red[1024];
    int t = threadIdx.x;
    red[t] = g_partials[t] + g_partials[t + 1024];
    __syncthreads();
    #pragma unroll
    for (int s = 512; s; s >>= 1) {
        if (t < s) red[t] += red[t + s];
        __syncthreads();
    }
    if (t == 0)
        out[(size_t)M_ROWS * DIM] = 2.0f * red[0] / (float)(M_ROWS * DIM);
}

// ---------------------------------------------------------------------------
extern "C" void kernel_launch(void* const* d_in, const int* in_sizes, int n_in,
                              void* d_out, int out_size) {
    const float* z  = (const float*)d_in[0];
    const float* cb = (const float*)d_in[1];
    float* out = (float*)d_out;

    cudaFuncSetAttribute(argmin_tf32,
                         cudaFuncAttributeMaxDynamicSharedMemorySize, SM_TOTAL);

    prepack_kernel <<<256, 256>>>(cb);
    cnorm_kernel   <<<KCODES / 8, 256>>>(cb);
    argmin_tf32    <<<M_ROWS / 64, 256, SM_TOTAL>>>(z, cb);
    recheck_kernel <<<64, 256>>>(z, cb);
    gather_kernel  <<<2048, 256>>>(z, cb, out);
    finalize_kernel<<<1, 1024>>>(out);
}